// round 8
// baseline (speedup 1.0000x reference)
#include <cuda_runtime.h>
#include <cuda_bf16.h>
#include <math.h>

// ============================================================================
// VNETDetector: K1 NN+softmax -> llrs (parallel); K2 sequential ACS scan
// (single consumer thread, software-pipelined 16-step asm blocks: MINs of
// step j-1 interleaved with FFMA2 of step j so fma/alu pipes alternate);
// K3 bit extraction by bit-exact checkpoint replay (parallel).
// ============================================================================

#define T_CAP      250112               // multiple of 128 and 16, >= 250000
#define SEG_STEPS  128
#define NSEG       4                    // ring: 4 * 128 * 64B = 32 KB
#define CKPT_STRIDE 16

// llr rows stored interleaved per t (16 floats = 4 float4 = 8 packed pairs):
//   q0 = (l0,l1),(l8,l9)   q1 = (l2,l3),(l10,l11)
//   q2 = (l4,l5),(l12,l13) q3 = (l6,l7),(l14,l15)
__device__ __align__(16) float4 g_llr4[T_CAP * 4];                  // 16 MB
__device__ __align__(16) float4 g_ckpt[(T_CAP / CKPT_STRIDE) * 2];  // 32B per ckpt

// ---------------- scalar ACS step (tail path + K3 replay; bit-exact twin) ---
__device__ __forceinline__ void acs_step_scalar(
    float& w0, float& w1, float& w2, float& w3,
    float& w4, float& w5, float& w6, float& w7,
    float4 q0, float4 q1, float4 q2, float4 q3)
{
    float nw0 = fminf(__fadd_rn(w0, q0.x), __fadd_rn(w1, q0.y));
    float nw4 = fminf(__fadd_rn(w0, q0.z), __fadd_rn(w1, q0.w));
    float nw1 = fminf(__fadd_rn(w2, q1.x), __fadd_rn(w3, q1.y));
    float nw5 = fminf(__fadd_rn(w2, q1.z), __fadd_rn(w3, q1.w));
    float nw2 = fminf(__fadd_rn(w4, q2.x), __fadd_rn(w5, q2.y));
    float nw6 = fminf(__fadd_rn(w4, q2.z), __fadd_rn(w5, q2.w));
    float nw3 = fminf(__fadd_rn(w6, q3.x), __fadd_rn(w7, q3.y));
    float nw7 = fminf(__fadd_rn(w6, q3.z), __fadd_rn(w7, q3.w));
    w0 = nw0; w1 = nw1; w2 = nw2; w3 = nw3;
    w4 = nw4; w5 = nw5; w6 = nw6; w7 = nw7;
}

// ---------------- software-pipelined 16-step ACS block -----------------------
// Virtual reg generations per step j (PTX <16> array declarations, letter-
// ending prefixes only -- digit-ending prefixes break ptxas name binding):
//   La..Lh = packed llr pairs, Sa..Sh = packed sums (fma results),
//   y*/z* = unpacked sum halves, ma..mh = min results.
// fma.rn.f32x2 with multiplier (1.0,1.0) == lanewise FADD.RN (bit-exact).
// min.f32 == fminf. Pack movs use fresh dests for max elision freedom.

// Loads for step j (64B at offset j*64)
#define LDQ(j, o0, o1, o2, o3) \
  "ld.shared.v2.u64 {La" #j ",Lb" #j "}, [%4+" #o0 "];\n\t" \
  "ld.shared.v2.u64 {Lc" #j ",Ld" #j "}, [%4+" #o1 "];\n\t" \
  "ld.shared.v2.u64 {Le" #j ",Lf" #j "}, [%4+" #o2 "];\n\t" \
  "ld.shared.v2.u64 {Lg" #j ",Lh" #j "}, [%4+" #o3 "];\n\t"

// F groups of step j: sums from current packs %0..%3
#define FG1(j) \
  "fma.rn.f32x2 Sa" #j ", La" #j ", %5, %0;\n\t" \
  "fma.rn.f32x2 Sb" #j ", Lb" #j ", %5, %0;\n\t"
#define FG2(j) \
  "fma.rn.f32x2 Sc" #j ", Lc" #j ", %5, %1;\n\t" \
  "fma.rn.f32x2 Sd" #j ", Ld" #j ", %5, %1;\n\t"
#define FG3(j) \
  "fma.rn.f32x2 Se" #j ", Le" #j ", %5, %2;\n\t" \
  "fma.rn.f32x2 Sf" #j ", Lf" #j ", %5, %2;\n\t"
#define FG4(j) \
  "fma.rn.f32x2 Sg" #j ", Lg" #j ", %5, %3;\n\t" \
  "fma.rn.f32x2 Sh" #j ", Lh" #j ", %5, %3;\n\t"

// M groups of step j: mins of sums -> new packs
//   %0 = (nw0,nw1) from Sa,Sc ; %1 = (nw2,nw3) from Se,Sg
//   %2 = (nw4,nw5) from Sb,Sd ; %3 = (nw6,nw7) from Sf,Sh
#define MG1(j) \
  "mov.b64 {ya" #j ",za" #j "}, Sa" #j ";\n\t" \
  "mov.b64 {yc" #j ",zc" #j "}, Sc" #j ";\n\t" \
  "min.f32 ma" #j ", ya" #j ", za" #j ";\n\t" \
  "min.f32 mb" #j ", yc" #j ", zc" #j ";\n\t" \
  "mov.b64 %0, {ma" #j ",mb" #j "};\n\t"
#define MG2(j) \
  "mov.b64 {ye" #j ",ze" #j "}, Se" #j ";\n\t" \
  "mov.b64 {yg" #j ",zg" #j "}, Sg" #j ";\n\t" \
  "min.f32 mc" #j ", ye" #j ", ze" #j ";\n\t" \
  "min.f32 md" #j ", yg" #j ", zg" #j ";\n\t" \
  "mov.b64 %1, {mc" #j ",md" #j "};\n\t"
#define MG3(j) \
  "mov.b64 {yb" #j ",zb" #j "}, Sb" #j ";\n\t" \
  "mov.b64 {yd" #j ",zd" #j "}, Sd" #j ";\n\t" \
  "min.f32 me" #j ", yb" #j ", zb" #j ";\n\t" \
  "min.f32 mf" #j ", yd" #j ", zd" #j ";\n\t" \
  "mov.b64 %2, {me" #j ",mf" #j "};\n\t"
#define MG4(j) \
  "mov.b64 {yf" #j ",zf" #j "}, Sf" #j ";\n\t" \
  "mov.b64 {yh" #j ",zh" #j "}, Sh" #j ";\n\t" \
  "min.f32 mg" #j ", yf" #j ", zf" #j ";\n\t" \
  "min.f32 mh" #j ", yh" #j ", zh" #j ";\n\t" \
  "mov.b64 %3, {mg" #j ",mh" #j "};\n\t"

// Interleaved: M groups of step jp feed the F groups of step j immediately.
#define MF(jp, j) \
  MG1(jp) FG1(j) MG2(jp) FG2(j) MG3(jp) FG3(j) MG4(jp) FG4(j)
#define FALL(j)  FG1(j) FG2(j) FG3(j) FG4(j)
#define MALL(j)  MG1(j) MG2(j) MG3(j) MG4(j)

#define ACS16(P01, P23, P45, P67, SADDR, ONE2)                              \
  asm volatile("{\n\t"                                                      \
    ".reg .b64 La<16>,Lb<16>,Lc<16>,Ld<16>,Le<16>,Lf<16>,Lg<16>,Lh<16>;\n\t" \
    ".reg .b64 Sa<16>,Sb<16>,Sc<16>,Sd<16>,Se<16>,Sf<16>,Sg<16>,Sh<16>;\n\t" \
    ".reg .f32 ya<16>,za<16>,yb<16>,zb<16>,yc<16>,zc<16>,yd<16>,zd<16>;\n\t" \
    ".reg .f32 ye<16>,ze<16>,yf<16>,zf<16>,yg<16>,zg<16>,yh<16>,zh<16>;\n\t" \
    ".reg .f32 ma<16>,mb<16>,mc<16>,md<16>,me<16>,mf<16>,mg<16>,mh<16>;\n\t" \
    LDQ(0, 0, 16, 32, 48)                                                   \
    LDQ(1, 64, 80, 96, 112)                                                 \
    FALL(0)                                                                 \
    LDQ(2, 128, 144, 160, 176)   MF(0, 1)                                   \
    LDQ(3, 192, 208, 224, 240)   MF(1, 2)                                   \
    LDQ(4, 256, 272, 288, 304)   MF(2, 3)                                   \
    LDQ(5, 320, 336, 352, 368)   MF(3, 4)                                   \
    LDQ(6, 384, 400, 416, 432)   MF(4, 5)                                   \
    LDQ(7, 448, 464, 480, 496)   MF(5, 6)                                   \
    LDQ(8, 512, 528, 544, 560)   MF(6, 7)                                   \
    LDQ(9, 576, 592, 608, 624)   MF(7, 8)                                   \
    LDQ(10, 640, 656, 672, 688)  MF(8, 9)                                   \
    LDQ(11, 704, 720, 736, 752)  MF(9, 10)                                  \
    LDQ(12, 768, 784, 800, 816)  MF(10, 11)                                 \
    LDQ(13, 832, 848, 864, 880)  MF(11, 12)                                 \
    LDQ(14, 896, 912, 928, 944)  MF(12, 13)                                 \
    LDQ(15, 960, 976, 992, 1008) MF(13, 14)                                 \
    MF(14, 15)                                                              \
    MALL(15)                                                                \
    "}"                                                                     \
    : "+l"(P01), "+l"(P23), "+l"(P45), "+l"(P67)                            \
    : "r"(SADDR), "l"(ONE2)                                                 \
    : "memory")

// ============================================================================
// K1: per-t NN forward, log_softmax -> llrs (interleaved), argmax bit + max prob
// ============================================================================
__global__ __launch_bounds__(128)
void k1_llr(const float* __restrict__ rx,
            const float* __restrict__ W1, const float* __restrict__ b1,
            const float* __restrict__ W2, const float* __restrict__ b2,
            float* __restrict__ out_cbits, float* __restrict__ out_conf, int T)
{
    __shared__ float sW1[100], sb1[100], sW2[1600], sb2[16];
    for (int k = threadIdx.x; k < 100;  k += blockDim.x) { sW1[k] = W1[k]; sb1[k] = b1[k]; }
    for (int k = threadIdx.x; k < 1600; k += blockDim.x) { sW2[k] = W2[k]; }
    for (int k = threadIdx.x; k < 16;   k += blockDim.x) { sb2[k] = b2[k]; }
    __syncthreads();

    int t = blockIdx.x * blockDim.x + threadIdx.x;
    if (t >= T) return;

    float x = rx[t];

    float acc[16];
#pragma unroll
    for (int i = 0; i < 16; i++) acc[i] = 0.0f;

#pragma unroll 4
    for (int j = 0; j < 100; j++) {
        float h = fmaxf(__fadd_rn(__fmul_rn(x, sW1[j]), sb1[j]), 0.0f);
#pragma unroll
        for (int i = 0; i < 16; i++)
            acc[i] = __fmaf_rn(h, sW2[i * 100 + j], acc[i]);
    }
#pragma unroll
    for (int i = 0; i < 16; i++) acc[i] = __fadd_rn(acc[i], sb2[i]);

    float m = acc[0];
#pragma unroll
    for (int i = 1; i < 16; i++) m = fmaxf(m, acc[i]);

    float sh[16];
    float S = 0.0f;
#pragma unroll
    for (int i = 0; i < 16; i++) {
        sh[i] = __fadd_rn(acc[i], -m);
        S = __fadd_rn(S, expf(sh[i]));
    }
    float lse = logf(S);

    float llr[16];
    float best = -1.0f;
    int bi = 0;
#pragma unroll
    for (int i = 0; i < 16; i++) {
        float lp = __fadd_rn(sh[i], -lse);
        llr[i] = -lp;
        float p = expf(lp);
        if (p > best) { best = p; bi = i; }   // strict > keeps first occurrence
    }

    out_cbits[t] = (float)(bi & 1);
    out_conf[t]  = best;

    float4* dst = g_llr4 + (size_t)t * 4;
    dst[0] = make_float4(llr[0], llr[1], llr[8],  llr[9]);
    dst[1] = make_float4(llr[2], llr[3], llr[10], llr[11]);
    dst[2] = make_float4(llr[4], llr[5], llr[12], llr[13]);
    dst[3] = make_float4(llr[6], llr[7], llr[14], llr[15]);
}

// ============================================================================
// K2: sequential ACS scan. 1 block, 128 threads.
//   warp 0 / lane 0 : consumer chain (SMSP 0, exclusive issue port)
//   warps 1..3      : producers (fill llr ring + flush checkpoint slots)
// ============================================================================
__global__ __launch_bounds__(128, 1)
void k2_scan(int T)
{
    __shared__ __align__(16) float4 ring[NSEG * SEG_STEPS * 4];      // 32 KB
    __shared__ __align__(16) ulonglong2 ck_smem[NSEG * 16];          // 8 ckpts*32B per slot
    __shared__ volatile int s_ready[NSEG];
    __shared__ volatile int s_freed[NSEG];

    int tid  = threadIdx.x;
    int wid  = tid >> 5;
    int lane = tid & 31;

    if (tid < NSEG) { s_ready[tid] = 0; s_freed[tid] = 0; }
    __syncthreads();

    int nSegs = (T + SEG_STEPS - 1) / SEG_STEPS;

    if (wid >= 1) {
        // ------------------ producers ------------------
        for (int s = wid - 1; s < nSegs; s += 3) {
            int slot = s & (NSEG - 1);
            if (lane == 0) {
                while (s_freed[slot] < s + 1 - NSEG) __nanosleep(64);
            }
            __syncwarp();
            // flush checkpoints of the seg that last used this slot (consumer
            // finished it before raising s_freed, so ck_smem[slot] is final)
            if (s >= NSEG) {
                const unsigned long long* cs =
                    reinterpret_cast<const unsigned long long*>(ck_smem + slot * 16);
                unsigned long long* cg =
                    reinterpret_cast<unsigned long long*>(g_ckpt) + (size_t)(s - NSEG) * 32;
                cg[lane] = cs[lane];
            }
            const float4* src = g_llr4 + (size_t)s * SEG_STEPS * 4;
            float4* dst = ring + slot * SEG_STEPS * 4;
#pragma unroll
            for (int k = 0; k < (SEG_STEPS * 4) / 32; k++)
                dst[k * 32 + lane] = src[k * 32 + lane];
            __syncwarp();
            __threadfence_block();
            if (lane == 0) s_ready[slot] = s + 1;
        }
    } else if (tid == 0) {
        // ------------------ consumer (the chain) ------------------
        unsigned long long P01 = 0ull, P23 = 0ull, P45 = 0ull, P67 = 0ull;
        const unsigned long long ONE2 = 0x3F8000003F800000ULL;   // (1.0f, 1.0f)

        unsigned ring0 = (unsigned)__cvta_generic_to_shared(ring);
        unsigned ck0   = (unsigned)__cvta_generic_to_shared(ck_smem);

        for (int s = 0; s < nSegs; s++) {
            int slot = s & (NSEG - 1);
            while (s_ready[slot] < s + 1) { /* spin */ }
            __threadfence_block();

            unsigned saddr  = ring0 + slot * (SEG_STEPS * 64);
            unsigned ckaddr = ck0   + slot * 256;
            int steps = min(SEG_STEPS, T - s * SEG_STEPS);

            if (steps == SEG_STEPS) {
                // 8 blocks of 16 steps; ckpt (2x STS.128) then one asm block
#pragma unroll 1
                for (int blk = 0; blk < 8; blk++) {
                    asm volatile(
                        "st.shared.v2.u64 [%0], {%1, %2};\n\t"
                        "st.shared.v2.u64 [%0+16], {%3, %4};\n\t"
                        :: "r"(ckaddr + blk * 32),
                           "l"(P01), "l"(P23), "l"(P45), "l"(P67)
                        : "memory");
                    ACS16(P01, P23, P45, P67, saddr + blk * 1024, ONE2);
                }
            } else {
                // ---- tail seg (steps < 128, multiple of 16 for T=250000) ----
                float w0, w1, w2, w3, w4, w5, w6, w7;
                asm("mov.b64 {%0,%1}, %4;\n\t mov.b64 {%2,%3}, %5;"
                    : "=f"(w0), "=f"(w1), "=f"(w2), "=f"(w3)
                    : "l"(P01), "l"(P23));
                asm("mov.b64 {%0,%1}, %4;\n\t mov.b64 {%2,%3}, %5;"
                    : "=f"(w4), "=f"(w5), "=f"(w6), "=f"(w7)
                    : "l"(P45), "l"(P67));
                const float4* sp = ring + slot * SEG_STEPS * 4;
                for (int j = 0; j < steps; j++) {
                    if ((j & 15) == 0) {
                        ulonglong2* ckb = ck_smem + slot * 16 + (j >> 4) * 2;
                        float4* cf = reinterpret_cast<float4*>(ckb);
                        cf[0] = make_float4(w0, w1, w2, w3);
                        cf[1] = make_float4(w4, w5, w6, w7);
                    }
                    const float4* q = sp + j * 4;
                    acs_step_scalar(w0, w1, w2, w3, w4, w5, w6, w7,
                                    q[0], q[1], q[2], q[3]);
                }
                asm("mov.b64 %0, {%2,%3};\n\t mov.b64 %1, {%4,%5};"
                    : "=l"(P01), "=l"(P23)
                    : "f"(w0), "f"(w1), "f"(w2), "f"(w3));
                asm("mov.b64 %0, {%2,%3};\n\t mov.b64 %1, {%4,%5};"
                    : "=l"(P45), "=l"(P67)
                    : "f"(w4), "f"(w5), "f"(w6), "f"(w7));
            }

            __threadfence_block();
            s_freed[slot] = s + 1;
        }

        // flush checkpoints of the last up-to-NSEG segs (their slots are never
        // reused by a producer)
        int s0 = (nSegs > NSEG) ? (nSegs - NSEG) : 0;
        for (int s = s0; s < nSegs; s++) {
            int slot = s & (NSEG - 1);
            const unsigned long long* cs =
                reinterpret_cast<const unsigned long long*>(ck_smem + slot * 16);
            unsigned long long* cg =
                reinterpret_cast<unsigned long long*>(g_ckpt) + (size_t)s * 32;
            for (int k = 0; k < 32; k++) cg[k] = cs[k];
        }
    }
}

// ============================================================================
// K3: replay each 16-step chunk from its checkpoint, emit detected bits.
// Bit-exact: scalar __fadd_rn / fminf == lanewise fma(l,1,w) / min.f32.
// ============================================================================
__global__ __launch_bounds__(128)
void k3_bits(float* __restrict__ out_bits, int T)
{
    int c = blockIdx.x * blockDim.x + threadIdx.x;
    int t0 = c * CKPT_STRIDE;
    if (t0 >= T) return;

    float4 c0 = g_ckpt[(size_t)c * 2 + 0];
    float4 c1 = g_ckpt[(size_t)c * 2 + 1];
    float w0 = c0.x, w1 = c0.y, w2 = c0.z, w3 = c0.w;
    float w4 = c1.x, w5 = c1.y, w6 = c1.z, w7 = c1.w;

    int n = min(CKPT_STRIDE, T - t0);
    for (int j = 0; j < n; j++) {
        float best = w0; int bi = 0;
        if (w1 < best) { best = w1; bi = 1; }
        if (w2 < best) { best = w2; bi = 2; }
        if (w3 < best) { best = w3; bi = 3; }
        if (w4 < best) { best = w4; bi = 4; }
        if (w5 < best) { best = w5; bi = 5; }
        if (w6 < best) { best = w6; bi = 6; }
        if (w7 < best) { best = w7; bi = 7; }
        out_bits[t0 + j] = (float)(bi & 1);

        const float4* q = g_llr4 + (size_t)(t0 + j) * 4;
        acs_step_scalar(w0, w1, w2, w3, w4, w5, w6, w7,
                        q[0], q[1], q[2], q[3]);
    }
}

// ============================================================================
extern "C" void kernel_launch(void* const* d_in, const int* in_sizes, int n_in,
                              void* d_out, int out_size)
{
    const float* rx = (const float*)d_in[0];
    const float* W1 = (const float*)d_in[1];
    const float* b1 = (const float*)d_in[2];
    const float* W2 = (const float*)d_in[3];
    const float* b2 = (const float*)d_in[4];
    int T = in_sizes[0];

    float* out = (float*)d_out;
    int sections = (T > 0) ? (out_size / T) : 0;
    float* out_det = out;
    float* out_cb  = (sections >= 2) ? out + T     : out;
    float* out_cw  = (sections >= 3) ? out + 2 * T : out_cb;

    int grid1 = (T + 127) / 128;
    k1_llr<<<grid1, 128>>>(rx, W1, b1, W2, b2, out_cb, out_cw, T);

    k2_scan<<<1, 128>>>(T);

    int nChunks = (T + CKPT_STRIDE - 1) / CKPT_STRIDE;
    int grid3 = (nChunks + 127) / 128;
    k3_bits<<<grid3, 128>>>(out_det, T);
}